// round 9
// baseline (speedup 1.0000x reference)
#include <cuda_runtime.h>
#include <cuda_fp16.h>
#include <cstdint>
#include <cstddef>

#define HID      512
#define BATCHSZ  65536
#define BM       128
#define BN       128
#define BK       64          // halves per K chunk
#define NK       24          // 1536 / 64
#define STAGES   3
#define NTH      128

// ---------------- fp16 scratch (device globals; no allocation allowed) ----------------
__device__ __align__(16) __half g_x16 [(size_t)BATCHSZ * HID];
__device__ __align__(16) __half g_s16 [(size_t)BATCHSZ * HID];
__device__ __align__(16) __half g_p16 [(size_t)BATCHSZ * HID];
__device__ __align__(16) __half g_hr16[(size_t)BATCHSZ * HID];
__device__ __align__(16) __half g_pr16[(size_t)BATCHSZ * HID];
__device__ __align__(16) __half g_w16 [12 * (size_t)HID * HID];  // [gate(a,r,r1,c)][sec(w,u,p)]
__device__ __align__(16) __half g_att [(size_t)BATCHSZ * HID];   // att gate, fp16

static __device__ __forceinline__ uint32_t smem_u32(const void* p) {
    uint32_t a;
    asm("{ .reg .u64 t; cvta.to.shared.u64 t, %1; cvt.u32.u64 %0, t; }" : "=r"(a) : "l"(p));
    return a;
}
static __device__ __forceinline__ float sigf(float x) {
    return __fdividef(1.0f, 1.0f + __expf(-x));
}
static __device__ __forceinline__ float tanhf_fast(float x) {
    return 1.0f - __fdividef(2.0f, __expf(2.0f * x) + 1.0f);
}

// ---------------- convert kernels ----------------
struct CvtW {
    const float* src[12];
    __half* dst[12];
};
__global__ void __launch_bounds__(256) cvt_w_kernel(CvtW a) {
    size_t stride = (size_t)gridDim.x * blockDim.x;
    for (size_t u = (size_t)blockIdx.x * blockDim.x + threadIdx.x; u < 786432u; u += stride) {
        int idx = (int)(u >> 16);
        size_t off = u & 65535u;
        float4 f = *((const float4*)a.src[idx] + off);
        __half2 h0 = __floats2half2_rn(f.x, f.y);
        __half2 h1 = __floats2half2_rn(f.z, f.w);
        uint2 pk = { *(uint32_t*)&h0, *(uint32_t*)&h1 };
        *((uint2*)a.dst[idx] + off) = pk;
    }
}
struct CvtB {
    const float* src[3];
    __half* dst[3];
};
#define BIG4 8388608u
__global__ void __launch_bounds__(256) cvt_b_kernel(CvtB a) {
    size_t stride = (size_t)gridDim.x * blockDim.x;
    for (size_t u = (size_t)blockIdx.x * blockDim.x + threadIdx.x; u < 3u * BIG4; u += stride) {
        int arr = (int)(u / BIG4);
        size_t off = u - (size_t)arr * BIG4;
        float4 f = *((const float4*)a.src[arr] + off);
        __half2 h0 = __floats2half2_rn(f.x, f.y);
        __half2 h1 = __floats2half2_rn(f.z, f.w);
        uint2 pk = { *(uint32_t*)&h0, *(uint32_t*)&h1 };
        *((uint2*)a.dst[arr] + off) = pk;
    }
}

// ---------------- GEMM ----------------
struct GArgs {
    const __half* A[3];        // K sections of virtual A
    const __half* B[3][3];     // [gate][sec]
    const float*  bias[3];
    const __half* s16;
    const __half* p16;
    __half* hr16;
    __half* pr16;
    __half* att;
    const float* state_f32;
    float*  out;
};

// smem: A stages [0, 3*16384), B stages [49152, 49152 + 3*16384). Total 96 KB -> 2 CTAs/SM.
#define SMEM_BYTES (STAGES * (16384 + 16384))

template <int PASS>
__global__ void __launch_bounds__(NTH, 2) gru_gemm(GArgs g) {
    extern __shared__ __align__(16) char sm[];
    const uint32_t smBase = smem_u32(sm);

    const int tid = threadIdx.x;
    const int wid = tid >> 5;
    const int lane = tid & 31;
    const int warp_m = wid & 1;      // 0..1 -> 64-row slice
    const int warp_n = wid >> 1;     // 0..1 -> 64-col slice
    const int m0 = blockIdx.y * BM;

    const int gate = (PASS == 1) ? (blockIdx.x >> 2) : 0;
    const int nInGate = (PASS == 1) ? ((blockIdx.x & 3) * BN) : (blockIdx.x * BN);

    const __half* Asec[3] = { g.A[0], g.A[1], g.A[2] };
    const __half* Bsec[3] = { g.B[gate][0], g.B[gate][1], g.B[gate][2] };

    // per stage: A 1024 16B chunks (128 rows x 8), B 1024 chunks; 16 per thread
    auto issue = [&](int ki, int stage) {
        const int sec = (ki * BK) >> 9;
        const int kin = ki * BK - sec * 512;         // halves
        const __half* Ag = Asec[sec];
        const __half* Bg = Bsec[sec];
        const uint32_t stA = smBase + stage * 16384;
        const uint32_t stB = smBase + STAGES * 16384 + stage * 16384;
#pragma unroll
        for (int i = 0; i < 16; ++i) {
            int q = tid + i * 128;
            int qq = q & 1023;
            int row = qq >> 3, kc = qq & 7;
            uint32_t soff = (uint32_t)(row * 128 + ((kc ^ (row & 7)) << 4));
            if (q < 1024) {
                const __half* ga = Ag + (size_t)(m0 + row) * HID + kin + kc * 8;
                asm volatile("cp.async.cg.shared.global [%0], [%1], 16;"
                             :: "r"(stA + soff), "l"(ga));
            } else {
                const __half* gb = Bg + (size_t)(nInGate + row) * HID + kin + kc * 8;
                asm volatile("cp.async.cg.shared.global [%0], [%1], 16;"
                             :: "r"(stB + soff), "l"(gb));
            }
        }
        asm volatile("cp.async.commit_group;");
    };

    float acc[4][8][4];
#pragma unroll
    for (int a = 0; a < 4; ++a)
#pragma unroll
        for (int b = 0; b < 8; ++b)
#pragma unroll
            for (int c = 0; c < 4; ++c) acc[a][b][c] = 0.0f;

    // ldmatrix lane geometry (validated)
    const int rlA = lane & 15;
    const int khA = lane >> 4;
    const int nbo = (lane & 7) + ((lane >> 4) << 3);
    const int khB = (lane >> 3) & 1;
    const int swA = lane & 7;
    const int swB = nbo & 7;

    issue(0, 0);
    issue(1, 1);

    for (int ki = 0; ki < NK; ++ki) {
        if (ki < NK - 1) asm volatile("cp.async.wait_group 1;");
        else             asm volatile("cp.async.wait_group 0;");
        __syncthreads();
        if (ki + 2 < NK) issue(ki + 2, (ki + 2) % STAGES);

        const int stage = ki % STAGES;
        const uint32_t stA = smBase + stage * 16384;
        const uint32_t stB = smBase + STAGES * 16384 + stage * 16384;
#pragma unroll
        for (int ks = 0; ks < 4; ++ks) {
            uint32_t af[4][4];
            uint32_t bf[4][4];
#pragma unroll
            for (int mt = 0; mt < 4; ++mt) {
                uint32_t addr = stA
                    + (uint32_t)((warp_m * 64 + mt * 16 + rlA) * 128)
                    + (uint32_t)(((ks * 2 + khA) ^ swA) << 4);
                asm volatile("ldmatrix.sync.aligned.m8n8.x4.shared.b16 {%0,%1,%2,%3}, [%4];"
                             : "=r"(af[mt][0]), "=r"(af[mt][1]), "=r"(af[mt][2]), "=r"(af[mt][3])
                             : "r"(addr));
            }
#pragma unroll
            for (int np = 0; np < 4; ++np) {
                uint32_t addr = stB
                    + (uint32_t)((warp_n * 64 + np * 16 + nbo) * 128)
                    + (uint32_t)(((ks * 2 + khB) ^ swB) << 4);
                asm volatile("ldmatrix.sync.aligned.m8n8.x4.shared.b16 {%0,%1,%2,%3}, [%4];"
                             : "=r"(bf[np][0]), "=r"(bf[np][1]), "=r"(bf[np][2]), "=r"(bf[np][3])
                             : "r"(addr));
            }
#pragma unroll
            for (int mt = 0; mt < 4; ++mt) {
#pragma unroll
                for (int nt = 0; nt < 8; ++nt) {
                    uint32_t b0 = bf[nt >> 1][(nt & 1) * 2 + 0];
                    uint32_t b1 = bf[nt >> 1][(nt & 1) * 2 + 1];
                    asm volatile(
                        "mma.sync.aligned.m16n8k16.row.col.f32.f16.f16.f32 "
                        "{%0,%1,%2,%3}, {%4,%5,%6,%7}, {%8,%9}, {%0,%1,%2,%3};"
                        : "+f"(acc[mt][nt][0]), "+f"(acc[mt][nt][1]),
                          "+f"(acc[mt][nt][2]), "+f"(acc[mt][nt][3])
                        : "r"(af[mt][0]), "r"(af[mt][1]), "r"(af[mt][2]), "r"(af[mt][3]),
                          "r"(b0), "r"(b1));
                }
            }
        }
    }

    // ---------------- epilogue ----------------
    const int lrow = lane >> 2;
    const int lcol = (lane & 3) * 2;
    const float* biasp = g.bias[gate];

    float bv[8][2];
#pragma unroll
    for (int nt = 0; nt < 8; ++nt) {
        int cg = nInGate + warp_n * 64 + nt * 8 + lcol;
        bv[nt][0] = biasp[cg];
        bv[nt][1] = biasp[cg + 1];
    }

#pragma unroll
    for (int mt = 0; mt < 4; ++mt) {
#pragma unroll
        for (int p = 0; p < 2; ++p) {
            int row = m0 + warp_m * 64 + mt * 16 + lrow + p * 8;
#pragma unroll
            for (int nt = 0; nt < 8; ++nt) {
                int cg = nInGate + warp_n * 64 + nt * 8 + lcol;
                float x0 = acc[mt][nt][p * 2 + 0] + bv[nt][0];
                float x1 = acc[mt][nt][p * 2 + 1] + bv[nt][1];
                size_t idx = (size_t)row * HID + cg;
                if (PASS == 1) {
                    float s0 = sigf(x0), s1 = sigf(x1);
                    if (gate == 0) {
                        *(__half2*)&g.att[idx] = __floats2half2_rn(s0, s1);
                    } else if (gate == 1) {
                        __half2 sv = *(const __half2*)&g.s16[idx];
                        float2 f = __half22float2(sv);
                        *(__half2*)&g.hr16[idx] = __floats2half2_rn(f.x * s0, f.y * s1);
                    } else {
                        __half2 pv = *(const __half2*)&g.p16[idx];
                        float2 f = __half22float2(pv);
                        *(__half2*)&g.pr16[idx] = __floats2half2_rn(f.x * s0, f.y * s1);
                    }
                } else {
                    float c0 = tanhf_fast(x0), c1 = tanhf_fast(x1);
                    __half2 ah = *(const __half2*)&g.att[idx];
                    float2 a = __half22float2(ah);
                    float2 st = *(const float2*)&g.state_f32[idx];
                    float2 o;
                    o.x = a.x * c0 + st.x - a.x * st.x;
                    o.y = a.y * c1 + st.y - a.y * st.y;
                    *(float2*)&g.out[idx] = o;
                }
            }
        }
    }
}

extern "C" void kernel_launch(void* const* d_in, const int* in_sizes, int n_in,
                              void* d_out, int out_size) {
    const float* inputs = (const float*)d_in[0];
    const float* state  = (const float*)d_in[1];
    const float* parent = (const float*)d_in[2];

    void *px16, *ps16, *pp16, *phr, *ppr, *pw16, *patt;
    cudaGetSymbolAddress(&px16, g_x16);
    cudaGetSymbolAddress(&ps16, g_s16);
    cudaGetSymbolAddress(&pp16, g_p16);
    cudaGetSymbolAddress(&phr,  g_hr16);
    cudaGetSymbolAddress(&ppr,  g_pr16);
    cudaGetSymbolAddress(&pw16, g_w16);
    cudaGetSymbolAddress(&patt, g_att);

    __half* w16 = (__half*)pw16;
    const size_t WSZ = (size_t)HID * HID;

    // gate order a,r,r1,c ; sec order w,u,p
    const int wIdx[4] = {3, 5, 7, 9};
    const int uIdx[4] = {11, 12, 13, 14};
    const int pIdx[4] = {15, 16, 17, 18};

    CvtW cw;
    for (int gg = 0; gg < 4; ++gg) {
        cw.src[gg * 3 + 0] = (const float*)d_in[wIdx[gg]];
        cw.src[gg * 3 + 1] = (const float*)d_in[uIdx[gg]];
        cw.src[gg * 3 + 2] = (const float*)d_in[pIdx[gg]];
        for (int s = 0; s < 3; ++s)
            cw.dst[gg * 3 + s] = w16 + (size_t)(gg * 3 + s) * WSZ;
    }
    CvtB cb;
    cb.src[0] = inputs; cb.dst[0] = (__half*)px16;
    cb.src[1] = state;  cb.dst[1] = (__half*)ps16;
    cb.src[2] = parent; cb.dst[2] = (__half*)pp16;

    cudaFuncSetAttribute(gru_gemm<1>, cudaFuncAttributeMaxDynamicSharedMemorySize, SMEM_BYTES);
    cudaFuncSetAttribute(gru_gemm<2>, cudaFuncAttributeMaxDynamicSharedMemorySize, SMEM_BYTES);

    GArgs a1 = {};
    a1.A[0] = (const __half*)px16; a1.A[1] = (const __half*)ps16; a1.A[2] = (const __half*)pp16;
    for (int gg = 0; gg < 3; ++gg)
        for (int s = 0; s < 3; ++s)
            a1.B[gg][s] = w16 + (size_t)(gg * 3 + s) * WSZ;
    a1.bias[0] = (const float*)d_in[4];
    a1.bias[1] = (const float*)d_in[6];
    a1.bias[2] = (const float*)d_in[8];
    a1.s16 = (const __half*)ps16;
    a1.p16 = (const __half*)pp16;
    a1.hr16 = (__half*)phr;
    a1.pr16 = (__half*)ppr;
    a1.att = (__half*)patt;
    a1.state_f32 = state;
    a1.out = nullptr;

    GArgs a2 = {};
    a2.A[0] = (const __half*)px16; a2.A[1] = (const __half*)phr; a2.A[2] = (const __half*)ppr;
    for (int s = 0; s < 3; ++s) {
        a2.B[0][s] = w16 + (size_t)(9 + s) * WSZ;
        a2.B[1][s] = a2.B[0][s];
        a2.B[2][s] = a2.B[0][s];
    }
    a2.bias[0] = (const float*)d_in[10];
    a2.bias[1] = a2.bias[0];
    a2.bias[2] = a2.bias[0];
    a2.s16 = (const __half*)ps16;
    a2.p16 = (const __half*)pp16;
    a2.hr16 = (__half*)phr;
    a2.pr16 = (__half*)ppr;
    a2.att = (__half*)patt;
    a2.state_f32 = state;
    a2.out = (float*)d_out;

    cvt_w_kernel<<<768, 256>>>(cw);
    cvt_b_kernel<<<8192, 256>>>(cb);
    // Pass 1: gates a, r, r1  (12 N-bands of 128 over 1536 outputs)
    gru_gemm<1><<<dim3(12, BATCHSZ / BM), NTH, SMEM_BYTES>>>(a1);
    // Pass 2: gate c + final blend
    gru_gemm<2><<<dim3(4,  BATCHSZ / BM), NTH, SMEM_BYTES>>>(a2);
}

// round 12
// speedup vs baseline: 1.2512x; 1.2512x over previous
#include <cuda_runtime.h>
#include <cuda.h>
#include <cuda_fp16.h>
#include <cstdint>
#include <cstddef>

#define HID      512
#define BATCHSZ  65536
#define BM       128
#define BN       128
#define BK       64          // halves per K chunk
#define NK       24          // 1536 / 64
#define STAGES   3
#define NTH      256

// ---------------- fp16 scratch (device globals; no allocation allowed) ----------------
// g_a1 = [x | state | parent], g_a2 = [x | hr | pr1]  (each section 65536x512 f16)
__device__ __align__(1024) __half g_a1[3 * (size_t)BATCHSZ * HID];
__device__ __align__(1024) __half g_a2[3 * (size_t)BATCHSZ * HID];
__device__ __align__(1024) __half g_w16[12 * (size_t)HID * HID];  // [gate(a,r,r1,c)][sec(w,u,p)]
__device__ __align__(16)   __half g_att[(size_t)BATCHSZ * HID];

#define SECSZ ((size_t)BATCHSZ * HID)

static __device__ __forceinline__ uint32_t smem_u32(const void* p) {
    uint32_t a;
    asm("{ .reg .u64 t; cvta.to.shared.u64 t, %1; cvt.u32.u64 %0, t; }" : "=r"(a) : "l"(p));
    return a;
}
static __device__ __forceinline__ float sigf(float x) {
    return __fdividef(1.0f, 1.0f + __expf(-x));
}
static __device__ __forceinline__ float tanhf_fast(float x) {
    return 1.0f - __fdividef(2.0f, __expf(2.0f * x) + 1.0f);
}
static __device__ __forceinline__ void mbar_wait(uint32_t addr, uint32_t phase) {
    uint32_t done;
    asm volatile(
        "{\n\t.reg .pred p;\n\t"
        "mbarrier.try_wait.parity.acquire.cta.shared::cta.b64 p, [%1], %2;\n\t"
        "selp.b32 %0, 1, 0, p;\n\t}"
        : "=r"(done) : "r"(addr), "r"(phase) : "memory");
    while (!done) {
        asm volatile(
            "{\n\t.reg .pred p;\n\t"
            "mbarrier.try_wait.parity.acquire.cta.shared::cta.b64 p, [%1], %2, 0x989680;\n\t"
            "selp.b32 %0, 1, 0, p;\n\t}"
            : "=r"(done) : "r"(addr), "r"(phase) : "memory");
    }
}

// ---------------- convert kernels ----------------
struct CvtW {
    const float* src[12];
    __half* dst[12];
};
__global__ void __launch_bounds__(256) cvt_w_kernel(CvtW a) {
    size_t stride = (size_t)gridDim.x * blockDim.x;
    for (size_t u = (size_t)blockIdx.x * blockDim.x + threadIdx.x; u < 786432u; u += stride) {
        int idx = (int)(u >> 16);
        size_t off = u & 65535u;
        float4 f = *((const float4*)a.src[idx] + off);
        __half2 h0 = __floats2half2_rn(f.x, f.y);
        __half2 h1 = __floats2half2_rn(f.z, f.w);
        uint2 pk = { *(uint32_t*)&h0, *(uint32_t*)&h1 };
        *((uint2*)a.dst[idx] + off) = pk;
    }
}
struct CvtB {
    const float* src[3];
    __half* dst[3];
    __half* xdup;      // second destination for x (section 0 of g_a2)
};
#define BIG4 8388608u
__global__ void __launch_bounds__(256) cvt_b_kernel(CvtB a) {
    size_t stride = (size_t)gridDim.x * blockDim.x;
    for (size_t u = (size_t)blockIdx.x * blockDim.x + threadIdx.x; u < 3u * BIG4; u += stride) {
        int arr = (int)(u / BIG4);
        size_t off = u - (size_t)arr * BIG4;
        float4 f = *((const float4*)a.src[arr] + off);
        __half2 h0 = __floats2half2_rn(f.x, f.y);
        __half2 h1 = __floats2half2_rn(f.z, f.w);
        uint2 pk = { *(uint32_t*)&h0, *(uint32_t*)&h1 };
        *((uint2*)a.dst[arr] + off) = pk;
        if (arr == 0) *((uint2*)a.xdup + off) = pk;
    }
}

// ---------------- GEMM ----------------
struct GArgs {
    const float*  bias[3];
    const __half* s16;         // g_a1 sec 1
    const __half* p16;         // g_a1 sec 2
    __half* hr16;              // g_a2 sec 1
    __half* pr16;              // g_a2 sec 2
    __half* att;
    const float* state_f32;
    float*  out;
};

// smem: [0..48) mbarriers (full[3] @0,8,16; empty[3] @24,32,40); tiles @1024
// A stages 1024 + s*16384 ; B stages 1024 + 49152 + s*16384
#define SMEM_BYTES (1024 + STAGES * 2 * 16384)

template <int PASS>
__global__ void __launch_bounds__(NTH, 2) gru_gemm(
    const __grid_constant__ CUtensorMap tmA,
    const __grid_constant__ CUtensorMap tmB,
    GArgs g)
{
    extern __shared__ __align__(16) char sm[];
    const uint32_t smBase = smem_u32(sm);

    const int tid = threadIdx.x;
    const int wid = tid >> 5;
    const int lane = tid & 31;
    const int warp_m = wid & 1;      // 0..1 -> 64-row slice
    const int warp_n = wid >> 1;     // 0..3 -> 32-col slice
    const int m0 = blockIdx.y * BM;

    const int gate = (PASS == 1) ? (blockIdx.x >> 2) : 0;
    const int nInGate = (PASS == 1) ? ((blockIdx.x & 3) * BN) : (blockIdx.x * BN);
    const int matBase = (PASS == 1) ? gate * 3 : 9;

    // mbarrier init
    if (tid == 0) {
#pragma unroll
        for (int s = 0; s < STAGES; ++s) {
            asm volatile("mbarrier.init.shared.b64 [%0], %1;"
                         :: "r"(smBase + s * 8), "r"(1) : "memory");          // full
            asm volatile("mbarrier.init.shared.b64 [%0], %1;"
                         :: "r"(smBase + 24 + s * 8), "r"(NTH) : "memory");   // empty
        }
    }
    __syncthreads();

    auto produce = [&](int ki, int stage, int phase) {
        mbar_wait(smBase + 24 + stage * 8, (uint32_t)phase);
        uint32_t fb = smBase + stage * 8;
        asm volatile("mbarrier.arrive.expect_tx.shared.b64 _, [%0], %1;"
                     :: "r"(fb), "r"(32768) : "memory");
        int sec = ki >> 3;
        int kin = (ki & 7) * BK;
        uint32_t da = smBase + 1024 + stage * 16384;
        uint32_t db = smBase + 1024 + STAGES * 16384 + stage * 16384;
        asm volatile(
            "cp.async.bulk.tensor.3d.shared::cta.global.tile.mbarrier::complete_tx::bytes "
            "[%0], [%1, {%2, %3, %4}], [%5];"
            :: "r"(da), "l"(&tmA), "r"(kin), "r"(m0), "r"(sec), "r"(fb) : "memory");
        asm volatile(
            "cp.async.bulk.tensor.3d.shared::cta.global.tile.mbarrier::complete_tx::bytes "
            "[%0], [%1, {%2, %3, %4}], [%5];"
            :: "r"(db), "l"(&tmB), "r"(kin), "r"(nInGate), "r"(matBase + sec), "r"(fb) : "memory");
    };

    float acc[4][4][4];
#pragma unroll
    for (int a = 0; a < 4; ++a)
#pragma unroll
        for (int b = 0; b < 4; ++b)
#pragma unroll
            for (int c = 0; c < 4; ++c) acc[a][b][c] = 0.0f;

    // ldmatrix lane geometry (validated)
    const int rlA = lane & 15;
    const int khA = lane >> 4;
    const int nbo = (lane & 7) + ((lane >> 4) << 3);
    const int khB = (lane >> 3) & 1;
    const int swA = lane & 7;
    const int swB = nbo & 7;

    // prologue: producer issues chunks 0,1 (stages 0,1, producer phase 1 passes on virgin barrier)
    if (tid == 0) { produce(0, 0, 1); produce(1, 1, 1); }
    int pstage = 2, pphase = 1;
    int cstage = 0, cphase = 0;

    for (int ki = 0; ki < NK; ++ki) {
        if (tid == 0 && ki + 2 < NK) {
            produce(ki + 2, pstage, pphase);
            if (++pstage == STAGES) { pstage = 0; pphase ^= 1; }
        }
        // consumer: wait data ready
        mbar_wait(smBase + cstage * 8, (uint32_t)cphase);

        const uint32_t stA = smBase + 1024 + cstage * 16384;
        const uint32_t stB = smBase + 1024 + STAGES * 16384 + cstage * 16384;
#pragma unroll
        for (int ks = 0; ks < 4; ++ks) {
            uint32_t af[4][4];
            uint32_t bf[2][4];
#pragma unroll
            for (int mt = 0; mt < 4; ++mt) {
                uint32_t addr = stA
                    + (uint32_t)((warp_m * 64 + mt * 16 + rlA) * 128)
                    + (uint32_t)(((ks * 2 + khA) ^ swA) << 4);
                asm volatile("ldmatrix.sync.aligned.m8n8.x4.shared.b16 {%0,%1,%2,%3}, [%4];"
                             : "=r"(af[mt][0]), "=r"(af[mt][1]), "=r"(af[mt][2]), "=r"(af[mt][3])
                             : "r"(addr));
            }
#pragma unroll
            for (int np = 0; np < 2; ++np) {
                uint32_t addr = stB
                    + (uint32_t)((warp_n * 32 + np * 16 + nbo) * 128)
                    + (uint32_t)(((ks * 2 + khB) ^ swB) << 4);
                asm volatile("ldmatrix.sync.aligned.m8n8.x4.shared.b16 {%0,%1,%2,%3}, [%4];"
                             : "=r"(bf[np][0]), "=r"(bf[np][1]), "=r"(bf[np][2]), "=r"(bf[np][3])
                             : "r"(addr));
            }
#pragma unroll
            for (int mt = 0; mt < 4; ++mt) {
#pragma unroll
                for (int nt = 0; nt < 4; ++nt) {
                    uint32_t b0 = bf[nt >> 1][(nt & 1) * 2 + 0];
                    uint32_t b1 = bf[nt >> 1][(nt & 1) * 2 + 1];
                    asm volatile(
                        "mma.sync.aligned.m16n8k16.row.col.f32.f16.f16.f32 "
                        "{%0,%1,%2,%3}, {%4,%5,%6,%7}, {%8,%9}, {%0,%1,%2,%3};"
                        : "+f"(acc[mt][nt][0]), "+f"(acc[mt][nt][1]),
                          "+f"(acc[mt][nt][2]), "+f"(acc[mt][nt][3])
                        : "r"(af[mt][0]), "r"(af[mt][1]), "r"(af[mt][2]), "r"(af[mt][3]),
                          "r"(b0), "r"(b1));
                }
            }
        }
        // done reading this stage
        asm volatile("mbarrier.arrive.shared.b64 _, [%0];"
                     :: "r"(smBase + 24 + cstage * 8) : "memory");
        if (++cstage == STAGES) { cstage = 0; cphase ^= 1; }
    }

    // ---------------- epilogue ----------------
    const int lrow = lane >> 2;
    const int lcol = (lane & 3) * 2;
    const float* biasp = g.bias[gate];

    float bv[4][2];
#pragma unroll
    for (int nt = 0; nt < 4; ++nt) {
        int cg = nInGate + warp_n * 32 + nt * 8 + lcol;
        bv[nt][0] = biasp[cg];
        bv[nt][1] = biasp[cg + 1];
    }

#pragma unroll
    for (int mt = 0; mt < 4; ++mt) {
#pragma unroll
        for (int p = 0; p < 2; ++p) {
            int row = m0 + warp_m * 64 + mt * 16 + lrow + p * 8;
#pragma unroll
            for (int nt = 0; nt < 4; ++nt) {
                int cg = nInGate + warp_n * 32 + nt * 8 + lcol;
                float x0 = acc[mt][nt][p * 2 + 0] + bv[nt][0];
                float x1 = acc[mt][nt][p * 2 + 1] + bv[nt][1];
                size_t idx = (size_t)row * HID + cg;
                if (PASS == 1) {
                    float s0 = sigf(x0), s1 = sigf(x1);
                    if (gate == 0) {
                        *(__half2*)&g.att[idx] = __floats2half2_rn(s0, s1);
                    } else if (gate == 1) {
                        __half2 sv = *(const __half2*)&g.s16[idx];
                        float2 f = __half22float2(sv);
                        *(__half2*)&g.hr16[idx] = __floats2half2_rn(f.x * s0, f.y * s1);
                    } else {
                        __half2 pv = *(const __half2*)&g.p16[idx];
                        float2 f = __half22float2(pv);
                        *(__half2*)&g.pr16[idx] = __floats2half2_rn(f.x * s0, f.y * s1);
                    }
                } else {
                    float c0 = tanhf_fast(x0), c1 = tanhf_fast(x1);
                    __half2 ah = *(const __half2*)&g.att[idx];
                    float2 a = __half22float2(ah);
                    float2 st = *(const float2*)&g.state_f32[idx];
                    float2 o;
                    o.x = a.x * c0 + st.x - a.x * st.x;
                    o.y = a.y * c1 + st.y - a.y * st.y;
                    *(float2*)&g.out[idx] = o;
                }
            }
        }
    }
}

// ---------------- host ----------------
typedef CUresult (CUDAAPI *PFN_encodeTiled)(
    CUtensorMap*, CUtensorMapDataType, cuuint32_t, void*,
    const cuuint64_t*, const cuuint64_t*, const cuuint32_t*, const cuuint32_t*,
    CUtensorMapInterleave, CUtensorMapSwizzle, CUtensorMapL2promotion, CUtensorMapFloatOOBfill);

static PFN_encodeTiled get_encode_fn() {
    static PFN_encodeTiled fn = nullptr;
    if (!fn) {
        void* p = nullptr;
#if CUDART_VERSION >= 12000
        cudaDriverEntryPointQueryResult qr;
        cudaGetDriverEntryPoint("cuTensorMapEncodeTiled", &p, cudaEnableDefault, &qr);
#else
        cudaGetDriverEntryPoint("cuTensorMapEncodeTiled", &p, cudaEnableDefault);
#endif
        fn = (PFN_encodeTiled)p;
    }
    return fn;
}

static void make_map(CUtensorMap* m, void* base, uint64_t d0, uint64_t d1, uint64_t d2) {
    cuuint64_t dims[3] = { d0, d1, d2 };
    cuuint64_t strides[2] = { d0 * 2, d0 * d1 * 2 };
    cuuint32_t box[3] = { 64, 128, 1 };
    cuuint32_t es[3] = { 1, 1, 1 };
    get_encode_fn()(m, CU_TENSOR_MAP_DATA_TYPE_FLOAT16, 3, base,
                    dims, strides, box, es,
                    CU_TENSOR_MAP_INTERLEAVE_NONE, CU_TENSOR_MAP_SWIZZLE_128B,
                    CU_TENSOR_MAP_L2_PROMOTION_L2_128B, CU_TENSOR_MAP_FLOAT_OOB_FILL_NONE);
}

extern "C" void kernel_launch(void* const* d_in, const int* in_sizes, int n_in,
                              void* d_out, int out_size) {
    const float* inputs = (const float*)d_in[0];
    const float* state  = (const float*)d_in[1];
    const float* parent = (const float*)d_in[2];

    void *pa1, *pa2, *pw16, *patt;
    cudaGetSymbolAddress(&pa1,  g_a1);
    cudaGetSymbolAddress(&pa2,  g_a2);
    cudaGetSymbolAddress(&pw16, g_w16);
    cudaGetSymbolAddress(&patt, g_att);

    __half* a1h = (__half*)pa1;
    __half* a2h = (__half*)pa2;
    __half* w16 = (__half*)pw16;
    const size_t WSZ = (size_t)HID * HID;

    // gate order a,r,r1,c ; sec order w,u,p
    const int wIdx[4] = {3, 5, 7, 9};
    const int uIdx[4] = {11, 12, 13, 14};
    const int pIdx[4] = {15, 16, 17, 18};

    CvtW cw;
    for (int gg = 0; gg < 4; ++gg) {
        cw.src[gg * 3 + 0] = (const float*)d_in[wIdx[gg]];
        cw.src[gg * 3 + 1] = (const float*)d_in[uIdx[gg]];
        cw.src[gg * 3 + 2] = (const float*)d_in[pIdx[gg]];
        for (int s = 0; s < 3; ++s)
            cw.dst[gg * 3 + s] = w16 + (size_t)(gg * 3 + s) * WSZ;
    }
    CvtB cb;
    cb.src[0] = inputs; cb.dst[0] = a1h;             // x -> a1 sec0
    cb.src[1] = state;  cb.dst[1] = a1h + SECSZ;     // s -> a1 sec1
    cb.src[2] = parent; cb.dst[2] = a1h + 2 * SECSZ; // p -> a1 sec2
    cb.xdup = a2h;                                   // x -> a2 sec0 too

    CUtensorMap tmA1, tmA2, tmB;
    make_map(&tmA1, pa1, HID, BATCHSZ, 3);
    make_map(&tmA2, pa2, HID, BATCHSZ, 3);
    make_map(&tmB,  pw16, HID, HID, 12);

    cudaFuncSetAttribute(gru_gemm<1>, cudaFuncAttributeMaxDynamicSharedMemorySize, SMEM_BYTES);
    cudaFuncSetAttribute(gru_gemm<2>, cudaFuncAttributeMaxDynamicSharedMemorySize, SMEM_BYTES);

    GArgs a1 = {};
    a1.bias[0] = (const float*)d_in[4];
    a1.bias[1] = (const float*)d_in[6];
    a1.bias[2] = (const float*)d_in[8];
    a1.s16 = a1h + SECSZ;
    a1.p16 = a1h + 2 * SECSZ;
    a1.hr16 = a2h + SECSZ;
    a1.pr16 = a2h + 2 * SECSZ;
    a1.att = (__half*)patt;
    a1.state_f32 = state;
    a1.out = nullptr;

    GArgs a2 = a1;
    a2.bias[0] = (const float*)d_in[10];
    a2.bias[1] = a2.bias[0];
    a2.bias[2] = a2.bias[0];
    a2.out = (float*)d_out;

    cvt_w_kernel<<<768, 256>>>(cw);
    cvt_b_kernel<<<8192, 256>>>(cb);
    // Pass 1: gates a, r, r1  (12 N-bands of 128 over 1536 outputs)
    gru_gemm<1><<<dim3(12, BATCHSZ / BM), NTH, SMEM_BYTES>>>(tmA1, tmB, a1);
    // Pass 2: gate c + final blend
    gru_gemm<2><<<dim3(4,  BATCHSZ / BM), NTH, SMEM_BYTES>>>(tmA2, tmB, a2);
}

// round 14
// speedup vs baseline: 1.2923x; 1.0329x over previous
#include <cuda_runtime.h>
#include <cuda.h>
#include <cuda_fp16.h>
#include <cstdint>
#include <cstddef>

#define HID      512
#define BATCHSZ  65536
#define BM       128
#define BN       128
#define BK       64          // halves per K chunk
#define NK       24          // 1536 / 64
#define STAGES   3
#define NTH      256

// ---------------- fp16 scratch (device globals; no allocation allowed) ----------------
// g_a1 = [x | state | parent] (3 sections), g_a2 = [hr | pr1] (2 sections)
__device__ __align__(1024) __half g_a1[3 * (size_t)BATCHSZ * HID];
__device__ __align__(1024) __half g_a2[2 * (size_t)BATCHSZ * HID];
__device__ __align__(1024) __half g_w16[12 * (size_t)HID * HID];  // [gate(a,r,r1,c)][sec(w,u,p)]
__device__ __align__(16)   __half g_att[(size_t)BATCHSZ * HID];

#define SECSZ ((size_t)BATCHSZ * HID)

static __device__ __forceinline__ uint32_t smem_u32(const void* p) {
    uint32_t a;
    asm("{ .reg .u64 t; cvta.to.shared.u64 t, %1; cvt.u32.u64 %0, t; }" : "=r"(a) : "l"(p));
    return a;
}
static __device__ __forceinline__ float sigf(float x) {
    return __fdividef(1.0f, 1.0f + __expf(-x));
}
static __device__ __forceinline__ float tanhf_fast(float x) {
    return 1.0f - __fdividef(2.0f, __expf(2.0f * x) + 1.0f);
}
static __device__ __forceinline__ void mbar_wait(uint32_t addr, uint32_t phase) {
    uint32_t done;
    asm volatile(
        "{\n\t.reg .pred p;\n\t"
        "mbarrier.try_wait.parity.acquire.cta.shared::cta.b64 p, [%1], %2;\n\t"
        "selp.b32 %0, 1, 0, p;\n\t}"
        : "=r"(done) : "r"(addr), "r"(phase) : "memory");
    while (!done) {
        asm volatile(
            "{\n\t.reg .pred p;\n\t"
            "mbarrier.try_wait.parity.acquire.cta.shared::cta.b64 p, [%1], %2, 0x989680;\n\t"
            "selp.b32 %0, 1, 0, p;\n\t}"
            : "=r"(done) : "r"(addr), "r"(phase) : "memory");
    }
}

// ---------------- convert kernels ----------------
struct CvtW {
    const float* src[12];
    __half* dst[12];
};
__global__ void __launch_bounds__(256) cvt_w_kernel(CvtW a) {
    size_t stride = (size_t)gridDim.x * blockDim.x;
    for (size_t u = (size_t)blockIdx.x * blockDim.x + threadIdx.x; u < 786432u; u += stride) {
        int idx = (int)(u >> 16);
        size_t off = u & 65535u;
        float4 f = *((const float4*)a.src[idx] + off);
        __half2 h0 = __floats2half2_rn(f.x, f.y);
        __half2 h1 = __floats2half2_rn(f.z, f.w);
        uint2 pk = { *(uint32_t*)&h0, *(uint32_t*)&h1 };
        *((uint2*)a.dst[idx] + off) = pk;
    }
}
struct CvtB {
    const float* src[3];
    __half* dst[3];
};
#define BIG4 8388608u
__global__ void __launch_bounds__(256) cvt_b_kernel(CvtB a) {
    size_t stride = (size_t)gridDim.x * blockDim.x;
    for (size_t u = (size_t)blockIdx.x * blockDim.x + threadIdx.x; u < 3u * BIG4; u += stride) {
        int arr = (int)(u / BIG4);
        size_t off = u - (size_t)arr * BIG4;
        float4 f = *((const float4*)a.src[arr] + off);
        __half2 h0 = __floats2half2_rn(f.x, f.y);
        __half2 h1 = __floats2half2_rn(f.z, f.w);
        uint2 pk = { *(uint32_t*)&h0, *(uint32_t*)&h1 };
        *((uint2*)a.dst[arr] + off) = pk;
    }
}

// ---------------- GEMM ----------------
struct GArgs {
    const float*  bias[3];
    const __half* s16;         // g_a1 sec 1
    const __half* p16;         // g_a1 sec 2
    __half* hr16;              // g_a2 sec 0
    __half* pr16;              // g_a2 sec 1
    __half* att;
    const float* state_f32;
    float*  out;
};

// smem: [0..48) mbarriers (full[3] @0,8,16; empty[3] @24,32,40); tiles @1024
// A stages 1024 + s*16384 ; B stages 1024 + 49152 + s*16384
#define SMEM_BYTES (1024 + STAGES * 2 * 16384)

// PASS 1: tmA covers g_a1 (3 sections, z=sec). tmA2 unused.
// PASS 2: sec 0 -> tmA (g_a1, z=0 = x); sec 1,2 -> tmA2 (g_a2, z=sec-1 = hr/pr).
template <int PASS>
__global__ void __launch_bounds__(NTH, 2) gru_gemm(
    const __grid_constant__ CUtensorMap tmA,
    const __grid_constant__ CUtensorMap tmA2,
    const __grid_constant__ CUtensorMap tmB,
    GArgs g)
{
    extern __shared__ __align__(16) char sm[];
    const uint32_t smBase = smem_u32(sm);

    const int tid = threadIdx.x;
    const int wid = tid >> 5;
    const int lane = tid & 31;
    const int warp_m = wid & 1;      // 0..1 -> 64-row slice
    const int warp_n = wid >> 1;     // 0..3 -> 32-col slice
    const int m0 = blockIdx.y * BM;

    const int gate = (PASS == 1) ? (blockIdx.x >> 2) : 0;
    const int nInGate = (PASS == 1) ? ((blockIdx.x & 3) * BN) : (blockIdx.x * BN);
    const int matBase = (PASS == 1) ? gate * 3 : 9;

    // mbarrier init: full count=1 (TMA tx), empty count=8 (one arrive per warp)
    if (tid == 0) {
#pragma unroll
        for (int s = 0; s < STAGES; ++s) {
            asm volatile("mbarrier.init.shared.b64 [%0], %1;"
                         :: "r"(smBase + s * 8), "r"(1) : "memory");          // full
            asm volatile("mbarrier.init.shared.b64 [%0], %1;"
                         :: "r"(smBase + 24 + s * 8), "r"(8) : "memory");     // empty
        }
    }
    __syncthreads();

    auto produce = [&](int ki, int stage, int phase) {
        mbar_wait(smBase + 24 + stage * 8, (uint32_t)phase);
        uint32_t fb = smBase + stage * 8;
        asm volatile("mbarrier.arrive.expect_tx.shared.b64 _, [%0], %1;"
                     :: "r"(fb), "r"(32768) : "memory");
        int sec = ki >> 3;
        int kin = (ki & 7) * BK;
        uint32_t da = smBase + 1024 + stage * 16384;
        uint32_t db = smBase + 1024 + STAGES * 16384 + stage * 16384;
        if (PASS == 1 || sec == 0) {
            int z = (PASS == 1) ? sec : 0;
            asm volatile(
                "cp.async.bulk.tensor.3d.shared::cta.global.tile.mbarrier::complete_tx::bytes "
                "[%0], [%1, {%2, %3, %4}], [%5];"
                :: "r"(da), "l"(&tmA), "r"(kin), "r"(m0), "r"(z), "r"(fb) : "memory");
        } else {
            asm volatile(
                "cp.async.bulk.tensor.3d.shared::cta.global.tile.mbarrier::complete_tx::bytes "
                "[%0], [%1, {%2, %3, %4}], [%5];"
                :: "r"(da), "l"(&tmA2), "r"(kin), "r"(m0), "r"(sec - 1), "r"(fb) : "memory");
        }
        asm volatile(
            "cp.async.bulk.tensor.3d.shared::cta.global.tile.mbarrier::complete_tx::bytes "
            "[%0], [%1, {%2, %3, %4}], [%5];"
            :: "r"(db), "l"(&tmB), "r"(kin), "r"(nInGate), "r"(matBase + sec), "r"(fb) : "memory");
    };

    float acc[4][4][4];
#pragma unroll
    for (int a = 0; a < 4; ++a)
#pragma unroll
        for (int b = 0; b < 4; ++b)
#pragma unroll
            for (int c = 0; c < 4; ++c) acc[a][b][c] = 0.0f;

    // ldmatrix lane geometry (validated)
    const int rlA = lane & 15;
    const int khA = lane >> 4;
    const int nbo = (lane & 7) + ((lane >> 4) << 3);
    const int khB = (lane >> 3) & 1;
    const int swA = lane & 7;
    const int swB = nbo & 7;

    // prologue: producer issues chunks 0,1 (stages 0,1, producer phase 1 passes on virgin barrier)
    if (tid == 0) { produce(0, 0, 1); produce(1, 1, 1); }
    int pphase = 1;   // producer phase for its next wait; stage sequence 2,0,1,...
    int cphase = 0;   // consumer phase

#pragma unroll 3
    for (int ki = 0; ki < NK; ++ki) {
        const int cstage = ki % STAGES;                 // constant after unroll-3
        if (tid == 0 && ki + 2 < NK) {
            const int pstage = (ki + 2) % STAGES;
            produce(ki + 2, pstage, pphase);
            if (pstage == STAGES - 1) pphase ^= 1;
        }
        // consumer: wait data ready
        mbar_wait(smBase + cstage * 8, (uint32_t)cphase);

        const uint32_t stA = smBase + 1024 + cstage * 16384;
        const uint32_t stB = smBase + 1024 + STAGES * 16384 + cstage * 16384;
#pragma unroll
        for (int ks = 0; ks < 4; ++ks) {
            uint32_t af[4][4];
            uint32_t bf[2][4];
#pragma unroll
            for (int mt = 0; mt < 4; ++mt) {
                uint32_t addr = stA
                    + (uint32_t)((warp_m * 64 + mt * 16 + rlA) * 128)
                    + (uint32_t)(((ks * 2 + khA) ^ swA) << 4);
                asm volatile("ldmatrix.sync.aligned.m8n8.x4.shared.b16 {%0,%1,%2,%3}, [%4];"
                             : "=r"(af[mt][0]), "=r"(af[mt][1]), "=r"(af[mt][2]), "=r"(af[mt][3])
                             : "r"(addr));
            }
#pragma unroll
            for (int np = 0; np < 2; ++np) {
                uint32_t addr = stB
                    + (uint32_t)((warp_n * 32 + np * 16 + nbo) * 128)
                    + (uint32_t)(((ks * 2 + khB) ^ swB) << 4);
                asm volatile("ldmatrix.sync.aligned.m8n8.x4.shared.b16 {%0,%1,%2,%3}, [%4];"
                             : "=r"(bf[np][0]), "=r"(bf[np][1]), "=r"(bf[np][2]), "=r"(bf[np][3])
                             : "r"(addr));
            }
#pragma unroll
            for (int mt = 0; mt < 4; ++mt) {
#pragma unroll
                for (int nt = 0; nt < 4; ++nt) {
                    uint32_t b0 = bf[nt >> 1][(nt & 1) * 2 + 0];
                    uint32_t b1 = bf[nt >> 1][(nt & 1) * 2 + 1];
                    asm volatile(
                        "mma.sync.aligned.m16n8k16.row.col.f32.f16.f16.f32 "
                        "{%0,%1,%2,%3}, {%4,%5,%6,%7}, {%8,%9}, {%0,%1,%2,%3};"
                        : "+f"(acc[mt][nt][0]), "+f"(acc[mt][nt][1]),
                          "+f"(acc[mt][nt][2]), "+f"(acc[mt][nt][3])
                        : "r"(af[mt][0]), "r"(af[mt][1]), "r"(af[mt][2]), "r"(af[mt][3]),
                          "r"(b0), "r"(b1));
                }
            }
        }
        // done reading this stage: one arrive per warp
        if (lane == 0)
            asm volatile("mbarrier.arrive.shared.b64 _, [%0];"
                         :: "r"(smBase + 24 + cstage * 8) : "memory");
        if (cstage == STAGES - 1) cphase ^= 1;
    }

    // ---------------- epilogue ----------------
    const int lrow = lane >> 2;
    const int lcol = (lane & 3) * 2;
    const float* biasp = g.bias[gate];

    float bv[4][2];
#pragma unroll
    for (int nt = 0; nt < 4; ++nt) {
        int cg = nInGate + warp_n * 32 + nt * 8 + lcol;
        bv[nt][0] = biasp[cg];
        bv[nt][1] = biasp[cg + 1];
    }

#pragma unroll
    for (int mt = 0; mt < 4; ++mt) {
#pragma unroll
        for (int p = 0; p < 2; ++p) {
            int row = m0 + warp_m * 64 + mt * 16 + lrow + p * 8;
#pragma unroll
            for (int nt = 0; nt < 4; ++nt) {
                int cg = nInGate + warp_n * 32 + nt * 8 + lcol;
                float x0 = acc[mt][nt][p * 2 + 0] + bv[nt][0];
                float x1 = acc[mt][nt][p * 2 + 1] + bv[nt][1];
                size_t idx = (size_t)row * HID + cg;
                if (PASS == 1) {
                    float s0 = sigf(x0), s1 = sigf(x1);
                    if (gate == 0) {
                        *(__half2*)&g.att[idx] = __floats2half2_rn(s0, s1);
                    } else if (gate == 1) {
                        __half2 sv = *(const __half2*)&g.s16[idx];
                        float2 f = __half22float2(sv);
                        *(__half2*)&g.hr16[idx] = __floats2half2_rn(f.x * s0, f.y * s1);
                    } else {
                        __half2 pv = *(const __half2*)&g.p16[idx];
                        float2 f = __half22float2(pv);
                        *(__half2*)&g.pr16[idx] = __floats2half2_rn(f.x * s0, f.y * s1);
                    }
                } else {
                    float c0 = tanhf_fast(x0), c1 = tanhf_fast(x1);
                    __half2 ah = *(const __half2*)&g.att[idx];
                    float2 a = __half22float2(ah);
                    float2 st = *(const float2*)&g.state_f32[idx];
                    float2 o;
                    o.x = a.x * c0 + st.x - a.x * st.x;
                    o.y = a.y * c1 + st.y - a.y * st.y;
                    *(float2*)&g.out[idx] = o;
                }
            }
        }
    }
}

// ---------------- host ----------------
typedef CUresult (CUDAAPI *PFN_encodeTiled)(
    CUtensorMap*, CUtensorMapDataType, cuuint32_t, void*,
    const cuuint64_t*, const cuuint64_t*, const cuuint32_t*, const cuuint32_t*,
    CUtensorMapInterleave, CUtensorMapSwizzle, CUtensorMapL2promotion, CUtensorMapFloatOOBfill);

static PFN_encodeTiled get_encode_fn() {
    static PFN_encodeTiled fn = nullptr;
    if (!fn) {
        void* p = nullptr;
#if CUDART_VERSION >= 12000
        cudaDriverEntryPointQueryResult qr;
        cudaGetDriverEntryPoint("cuTensorMapEncodeTiled", &p, cudaEnableDefault, &qr);
#else
        cudaGetDriverEntryPoint("cuTensorMapEncodeTiled", &p, cudaEnableDefault);
#endif
        fn = (PFN_encodeTiled)p;
    }
    return fn;
}

static void make_map(CUtensorMap* m, void* base, uint64_t d0, uint64_t d1, uint64_t d2) {
    cuuint64_t dims[3] = { d0, d1, d2 };
    cuuint64_t strides[2] = { d0 * 2, d0 * d1 * 2 };
    cuuint32_t box[3] = { 64, 128, 1 };
    cuuint32_t es[3] = { 1, 1, 1 };
    get_encode_fn()(m, CU_TENSOR_MAP_DATA_TYPE_FLOAT16, 3, base,
                    dims, strides, box, es,
                    CU_TENSOR_MAP_INTERLEAVE_NONE, CU_TENSOR_MAP_SWIZZLE_128B,
                    CU_TENSOR_MAP_L2_PROMOTION_L2_128B, CU_TENSOR_MAP_FLOAT_OOB_FILL_NONE);
}

extern "C" void kernel_launch(void* const* d_in, const int* in_sizes, int n_in,
                              void* d_out, int out_size) {
    const float* inputs = (const float*)d_in[0];
    const float* state  = (const float*)d_in[1];
    const float* parent = (const float*)d_in[2];

    void *pa1, *pa2, *pw16, *patt;
    cudaGetSymbolAddress(&pa1,  g_a1);
    cudaGetSymbolAddress(&pa2,  g_a2);
    cudaGetSymbolAddress(&pw16, g_w16);
    cudaGetSymbolAddress(&patt, g_att);

    __half* a1h = (__half*)pa1;
    __half* a2h = (__half*)pa2;
    __half* w16 = (__half*)pw16;
    const size_t WSZ = (size_t)HID * HID;

    // gate order a,r,r1,c ; sec order w,u,p
    const int wIdx[4] = {3, 5, 7, 9};
    const int uIdx[4] = {11, 12, 13, 14};
    const int pIdx[4] = {15, 16, 17, 18};

    CvtW cw;
    for (int gg = 0; gg < 4; ++gg) {
        cw.src[gg * 3 + 0] = (const float*)d_in[wIdx[gg]];
        cw.src[gg * 3 + 1] = (const float*)d_in[uIdx[gg]];
        cw.src[gg * 3 + 2] = (const float*)d_in[pIdx[gg]];
        for (int s = 0; s < 3; ++s)
            cw.dst[gg * 3 + s] = w16 + (size_t)(gg * 3 + s) * WSZ;
    }
    CvtB cb;
    cb.src[0] = inputs; cb.dst[0] = a1h;             // x -> a1 sec0
    cb.src[1] = state;  cb.dst[1] = a1h + SECSZ;     // s -> a1 sec1
    cb.src[2] = parent; cb.dst[2] = a1h + 2 * SECSZ; // p -> a1 sec2

    CUtensorMap tmA1, tmA2, tmB;
    make_map(&tmA1, pa1, HID, BATCHSZ, 3);   // [x|s|p]
    make_map(&tmA2, pa2, HID, BATCHSZ, 2);   // [hr|pr]
    make_map(&tmB,  pw16, HID, HID, 12);

    cudaFuncSetAttribute(gru_gemm<1>, cudaFuncAttributeMaxDynamicSharedMemorySize, SMEM_BYTES);
    cudaFuncSetAttribute(gru_gemm<2>, cudaFuncAttributeMaxDynamicSharedMemorySize, SMEM_BYTES);

    GArgs a1 = {};
    a1.bias[0] = (const float*)d_in[4];
    a1.bias[1] = (const float*)d_in[6];
    a1.bias[2] = (const float*)d_in[8];
    a1.s16 = a1h + SECSZ;
    a1.p16 = a1h + 2 * SECSZ;
    a1.hr16 = a2h;
    a1.pr16 = a2h + SECSZ;
    a1.att = (__half*)patt;
    a1.state_f32 = state;
    a1.out = nullptr;

    GArgs a2 = a1;
    a2.bias[0] = (const float*)d_in[10];
    a2.bias[1] = a2.bias[0];
    a2.bias[2] = a2.bias[0];
    a2.out = (float*)d_out;

    cvt_w_kernel<<<768, 256>>>(cw);
    cvt_b_kernel<<<8192, 256>>>(cb);
    // Pass 1: gates a, r, r1  (12 N-bands of 128 over 1536 outputs)
    gru_gemm<1><<<dim3(12, BATCHSZ / BM), NTH, SMEM_BYTES>>>(tmA1, tmA2, tmB, a1);
    // Pass 2: gate c + final blend
    gru_gemm<2><<<dim3(4,  BATCHSZ / BM), NTH, SMEM_BYTES>>>(tmA1, tmA2, tmB, a2);
}

// round 15
// speedup vs baseline: 1.2931x; 1.0006x over previous
#include <cuda_runtime.h>
#include <cuda.h>
#include <cuda_fp16.h>
#include <cstdint>
#include <cstddef>

#define HID      512
#define BATCHSZ  65536
#define BM       128
#define BN       128
#define BK       64          // halves per K chunk
#define NK       24          // 1536 / 64
#define STAGES   3
#define NTH      256

// ---------------- fp16 scratch (device globals; no allocation allowed) ----------------
// g_a1 = [x | state | parent] (3 sections), g_a2 = [hr | pr1] (2 sections)
__device__ __align__(1024) __half g_a1[3 * (size_t)BATCHSZ * HID];
__device__ __align__(1024) __half g_a2[2 * (size_t)BATCHSZ * HID];
__device__ __align__(1024) __half g_w16[12 * (size_t)HID * HID];  // [gate(a,r,r1,c)][sec(w,u,p)]
__device__ __align__(16)   __half g_att[(size_t)BATCHSZ * HID];

#define SECSZ ((size_t)BATCHSZ * HID)

static __device__ __forceinline__ uint32_t smem_u32(const void* p) {
    uint32_t a;
    asm("{ .reg .u64 t; cvta.to.shared.u64 t, %1; cvt.u32.u64 %0, t; }" : "=r"(a) : "l"(p));
    return a;
}
static __device__ __forceinline__ float sigf(float x) {
    return __fdividef(1.0f, 1.0f + __expf(-x));
}
static __device__ __forceinline__ float tanhf_fast(float x) {
    return 1.0f - __fdividef(2.0f, __expf(2.0f * x) + 1.0f);
}
static __device__ __forceinline__ void mbar_wait(uint32_t addr, uint32_t phase) {
    uint32_t done;
    asm volatile(
        "{\n\t.reg .pred p;\n\t"
        "mbarrier.try_wait.parity.acquire.cta.shared::cta.b64 p, [%1], %2;\n\t"
        "selp.b32 %0, 1, 0, p;\n\t}"
        : "=r"(done) : "r"(addr), "r"(phase) : "memory");
    while (!done) {
        asm volatile(
            "{\n\t.reg .pred p;\n\t"
            "mbarrier.try_wait.parity.acquire.cta.shared::cta.b64 p, [%1], %2, 0x989680;\n\t"
            "selp.b32 %0, 1, 0, p;\n\t}"
            : "=r"(done) : "r"(addr), "r"(phase) : "memory");
    }
}

// ---------------- convert kernels ----------------
struct CvtW {
    const float* src[12];
    __half* dst[12];
};
__global__ void __launch_bounds__(256) cvt_w_kernel(CvtW a) {
    size_t stride = (size_t)gridDim.x * blockDim.x;
    for (size_t u = (size_t)blockIdx.x * blockDim.x + threadIdx.x; u < 786432u; u += stride) {
        int idx = (int)(u >> 16);
        size_t off = u & 65535u;
        float4 f = *((const float4*)a.src[idx] + off);
        __half2 h0 = __floats2half2_rn(f.x, f.y);
        __half2 h1 = __floats2half2_rn(f.z, f.w);
        uint2 pk = { *(uint32_t*)&h0, *(uint32_t*)&h1 };
        *((uint2*)a.dst[idx] + off) = pk;
    }
}
struct CvtB {
    const float* src[3];
    __half* dst[3];
};
#define BIG4 8388608u
__global__ void __launch_bounds__(256) cvt_b_kernel(CvtB a) {
    size_t stride = (size_t)gridDim.x * blockDim.x;
    for (size_t u = (size_t)blockIdx.x * blockDim.x + threadIdx.x; u < 3u * BIG4; u += stride) {
        int arr = (int)(u / BIG4);
        size_t off = u - (size_t)arr * BIG4;
        float4 f = *((const float4*)a.src[arr] + off);
        __half2 h0 = __floats2half2_rn(f.x, f.y);
        __half2 h1 = __floats2half2_rn(f.z, f.w);
        uint2 pk = { *(uint32_t*)&h0, *(uint32_t*)&h1 };
        *((uint2*)a.dst[arr] + off) = pk;
    }
}

// ---------------- GEMM ----------------
struct GArgs {
    const float*  bias[3];
    const __half* s16;         // g_a1 sec 1
    const __half* p16;         // g_a1 sec 2
    __half* hr16;              // g_a2 sec 0
    __half* pr16;              // g_a2 sec 1
    __half* att;
    const float* state_f32;
    float*  out;
};

// smem: [0..48) mbarriers (full[3] @0,8,16; empty[3] @24,32,40); tiles @1024
// A stages 1024 + s*16384 ; B stages 1024 + 49152 + s*16384
#define SMEM_BYTES (1024 + STAGES * 2 * 16384)

// PASS 1: tmA covers g_a1 (3 sections, z=sec). tmA2 unused.
// PASS 2: sec 0 -> tmA (g_a1, z=0 = x); sec 1,2 -> tmA2 (g_a2, z=sec-1 = hr/pr).
template <int PASS>
__global__ void __launch_bounds__(NTH, 2) gru_gemm(
    const __grid_constant__ CUtensorMap tmA,
    const __grid_constant__ CUtensorMap tmA2,
    const __grid_constant__ CUtensorMap tmB,
    GArgs g)
{
    extern __shared__ __align__(16) char sm[];
    const uint32_t smBase = smem_u32(sm);

    const int tid = threadIdx.x;
    const int wid = tid >> 5;
    const int lane = tid & 31;
    const int warp_m = wid & 1;      // 0..1 -> 64-row slice
    const int warp_n = wid >> 1;     // 0..3 -> 32-col slice
    const int m0 = blockIdx.y * BM;

    const int gate = (PASS == 1) ? (blockIdx.x >> 2) : 0;
    const int nInGate = (PASS == 1) ? ((blockIdx.x & 3) * BN) : (blockIdx.x * BN);
    const int matBase = (PASS == 1) ? gate * 3 : 9;

    // mbarrier init: full count=1 (TMA tx), empty count=8 (one arrive per warp)
    if (tid == 0) {
#pragma unroll
        for (int s = 0; s < STAGES; ++s) {
            asm volatile("mbarrier.init.shared.b64 [%0], %1;"
                         :: "r"(smBase + s * 8), "r"(1) : "memory");          // full
            asm volatile("mbarrier.init.shared.b64 [%0], %1;"
                         :: "r"(smBase + 24 + s * 8), "r"(8) : "memory");     // empty
        }
    }
    __syncthreads();

    auto produce = [&](int ki, int stage, int phase) {
        mbar_wait(smBase + 24 + stage * 8, (uint32_t)phase);
        uint32_t fb = smBase + stage * 8;
        asm volatile("mbarrier.arrive.expect_tx.shared.b64 _, [%0], %1;"
                     :: "r"(fb), "r"(32768) : "memory");
        int sec = ki >> 3;
        int kin = (ki & 7) * BK;
        uint32_t da = smBase + 1024 + stage * 16384;
        uint32_t db = smBase + 1024 + STAGES * 16384 + stage * 16384;
        if (PASS == 1 || sec == 0) {
            int z = (PASS == 1) ? sec : 0;
            asm volatile(
                "cp.async.bulk.tensor.3d.shared::cta.global.tile.mbarrier::complete_tx::bytes "
                "[%0], [%1, {%2, %3, %4}], [%5];"
                :: "r"(da), "l"(&tmA), "r"(kin), "r"(m0), "r"(z), "r"(fb) : "memory");
        } else {
            asm volatile(
                "cp.async.bulk.tensor.3d.shared::cta.global.tile.mbarrier::complete_tx::bytes "
                "[%0], [%1, {%2, %3, %4}], [%5];"
                :: "r"(da), "l"(&tmA2), "r"(kin), "r"(m0), "r"(sec - 1), "r"(fb) : "memory");
        }
        asm volatile(
            "cp.async.bulk.tensor.3d.shared::cta.global.tile.mbarrier::complete_tx::bytes "
            "[%0], [%1, {%2, %3, %4}], [%5];"
            :: "r"(db), "l"(&tmB), "r"(kin), "r"(nInGate), "r"(matBase + sec), "r"(fb) : "memory");
    };

    float acc[4][4][4];
#pragma unroll
    for (int a = 0; a < 4; ++a)
#pragma unroll
        for (int b = 0; b < 4; ++b)
#pragma unroll
            for (int c = 0; c < 4; ++c) acc[a][b][c] = 0.0f;

    // ldmatrix lane geometry (validated)
    const int rlA = lane & 15;
    const int khA = lane >> 4;
    const int nbo = (lane & 7) + ((lane >> 4) << 3);
    const int khB = (lane >> 3) & 1;
    const int swA = lane & 7;
    const int swB = nbo & 7;

    // prologue: producer issues chunks 0,1 (stages 0,1, producer phase 1 passes on virgin barrier)
    if (tid == 0) { produce(0, 0, 1); produce(1, 1, 1); }
    int pphase = 1;   // producer phase for its next wait; stage sequence 2,0,1,...
    int cphase = 0;   // consumer phase

#pragma unroll 3
    for (int ki = 0; ki < NK; ++ki) {
        const int cstage = ki % STAGES;                 // constant after unroll-3
        if (tid == 0 && ki + 2 < NK) {
            const int pstage = (ki + 2) % STAGES;
            produce(ki + 2, pstage, pphase);
            if (pstage == STAGES - 1) pphase ^= 1;
        }
        // consumer: wait data ready
        mbar_wait(smBase + cstage * 8, (uint32_t)cphase);

        const uint32_t stA = smBase + 1024 + cstage * 16384;
        const uint32_t stB = smBase + 1024 + STAGES * 16384 + cstage * 16384;
#pragma unroll
        for (int ks = 0; ks < 4; ++ks) {
            uint32_t af[4][4];
            uint32_t bf[2][4];
#pragma unroll
            for (int mt = 0; mt < 4; ++mt) {
                uint32_t addr = stA
                    + (uint32_t)((warp_m * 64 + mt * 16 + rlA) * 128)
                    + (uint32_t)(((ks * 2 + khA) ^ swA) << 4);
                asm volatile("ldmatrix.sync.aligned.m8n8.x4.shared.b16 {%0,%1,%2,%3}, [%4];"
                             : "=r"(af[mt][0]), "=r"(af[mt][1]), "=r"(af[mt][2]), "=r"(af[mt][3])
                             : "r"(addr));
            }
#pragma unroll
            for (int np = 0; np < 2; ++np) {
                uint32_t addr = stB
                    + (uint32_t)((warp_n * 32 + np * 16 + nbo) * 128)
                    + (uint32_t)(((ks * 2 + khB) ^ swB) << 4);
                asm volatile("ldmatrix.sync.aligned.m8n8.x4.shared.b16 {%0,%1,%2,%3}, [%4];"
                             : "=r"(bf[np][0]), "=r"(bf[np][1]), "=r"(bf[np][2]), "=r"(bf[np][3])
                             : "r"(addr));
            }
#pragma unroll
            for (int mt = 0; mt < 4; ++mt) {
#pragma unroll
                for (int nt = 0; nt < 4; ++nt) {
                    uint32_t b0 = bf[nt >> 1][(nt & 1) * 2 + 0];
                    uint32_t b1 = bf[nt >> 1][(nt & 1) * 2 + 1];
                    asm volatile(
                        "mma.sync.aligned.m16n8k16.row.col.f32.f16.f16.f32 "
                        "{%0,%1,%2,%3}, {%4,%5,%6,%7}, {%8,%9}, {%0,%1,%2,%3};"
                        : "+f"(acc[mt][nt][0]), "+f"(acc[mt][nt][1]),
                          "+f"(acc[mt][nt][2]), "+f"(acc[mt][nt][3])
                        : "r"(af[mt][0]), "r"(af[mt][1]), "r"(af[mt][2]), "r"(af[mt][3]),
                          "r"(b0), "r"(b1));
                }
            }
        }
        // done reading this stage: one arrive per warp
        if (lane == 0)
            asm volatile("mbarrier.arrive.shared.b64 _, [%0];"
                         :: "r"(smBase + 24 + cstage * 8) : "memory");
        if (cstage == STAGES - 1) cphase ^= 1;
    }

    // ---------------- epilogue ----------------
    const int lrow = lane >> 2;
    const int lcol = (lane & 3) * 2;
    const float* biasp = g.bias[gate];

    float bv[4][2];
#pragma unroll
    for (int nt = 0; nt < 4; ++nt) {
        int cg = nInGate + warp_n * 32 + nt * 8 + lcol;
        bv[nt][0] = biasp[cg];
        bv[nt][1] = biasp[cg + 1];
    }

#pragma unroll
    for (int mt = 0; mt < 4; ++mt) {
#pragma unroll
        for (int p = 0; p < 2; ++p) {
            int row = m0 + warp_m * 64 + mt * 16 + lrow + p * 8;
#pragma unroll
            for (int nt = 0; nt < 4; ++nt) {
                int cg = nInGate + warp_n * 32 + nt * 8 + lcol;
                float x0 = acc[mt][nt][p * 2 + 0] + bv[nt][0];
                float x1 = acc[mt][nt][p * 2 + 1] + bv[nt][1];
                size_t idx = (size_t)row * HID + cg;
                if (PASS == 1) {
                    float s0 = sigf(x0), s1 = sigf(x1);
                    if (gate == 0) {
                        *(__half2*)&g.att[idx] = __floats2half2_rn(s0, s1);
                    } else if (gate == 1) {
                        __half2 sv = *(const __half2*)&g.s16[idx];
                        float2 f = __half22float2(sv);
                        *(__half2*)&g.hr16[idx] = __floats2half2_rn(f.x * s0, f.y * s1);
                    } else {
                        __half2 pv = *(const __half2*)&g.p16[idx];
                        float2 f = __half22float2(pv);
                        *(__half2*)&g.pr16[idx] = __floats2half2_rn(f.x * s0, f.y * s1);
                    }
                } else {
                    float c0 = tanhf_fast(x0), c1 = tanhf_fast(x1);
                    __half2 ah = *(const __half2*)&g.att[idx];
                    float2 a = __half22float2(ah);
                    float2 st = *(const float2*)&g.state_f32[idx];
                    float2 o;
                    o.x = a.x * c0 + st.x - a.x * st.x;
                    o.y = a.y * c1 + st.y - a.y * st.y;
                    *(float2*)&g.out[idx] = o;
                }
            }
        }
    }
}

// ---------------- host ----------------
typedef CUresult (CUDAAPI *PFN_encodeTiled)(
    CUtensorMap*, CUtensorMapDataType, cuuint32_t, void*,
    const cuuint64_t*, const cuuint64_t*, const cuuint32_t*, const cuuint32_t*,
    CUtensorMapInterleave, CUtensorMapSwizzle, CUtensorMapL2promotion, CUtensorMapFloatOOBfill);

static PFN_encodeTiled get_encode_fn() {
    static PFN_encodeTiled fn = nullptr;
    if (!fn) {
        void* p = nullptr;
#if CUDART_VERSION >= 12000
        cudaDriverEntryPointQueryResult qr;
        cudaGetDriverEntryPoint("cuTensorMapEncodeTiled", &p, cudaEnableDefault, &qr);
#else
        cudaGetDriverEntryPoint("cuTensorMapEncodeTiled", &p, cudaEnableDefault);
#endif
        fn = (PFN_encodeTiled)p;
    }
    return fn;
}

static void make_map(CUtensorMap* m, void* base, uint64_t d0, uint64_t d1, uint64_t d2) {
    cuuint64_t dims[3] = { d0, d1, d2 };
    cuuint64_t strides[2] = { d0 * 2, d0 * d1 * 2 };
    cuuint32_t box[3] = { 64, 128, 1 };
    cuuint32_t es[3] = { 1, 1, 1 };
    get_encode_fn()(m, CU_TENSOR_MAP_DATA_TYPE_FLOAT16, 3, base,
                    dims, strides, box, es,
                    CU_TENSOR_MAP_INTERLEAVE_NONE, CU_TENSOR_MAP_SWIZZLE_128B,
                    CU_TENSOR_MAP_L2_PROMOTION_L2_128B, CU_TENSOR_MAP_FLOAT_OOB_FILL_NONE);
}

extern "C" void kernel_launch(void* const* d_in, const int* in_sizes, int n_in,
                              void* d_out, int out_size) {
    const float* inputs = (const float*)d_in[0];
    const float* state  = (const float*)d_in[1];
    const float* parent = (const float*)d_in[2];

    void *pa1, *pa2, *pw16, *patt;
    cudaGetSymbolAddress(&pa1,  g_a1);
    cudaGetSymbolAddress(&pa2,  g_a2);
    cudaGetSymbolAddress(&pw16, g_w16);
    cudaGetSymbolAddress(&patt, g_att);

    __half* a1h = (__half*)pa1;
    __half* a2h = (__half*)pa2;
    __half* w16 = (__half*)pw16;
    const size_t WSZ = (size_t)HID * HID;

    // gate order a,r,r1,c ; sec order w,u,p
    const int wIdx[4] = {3, 5, 7, 9};
    const int uIdx[4] = {11, 12, 13, 14};
    const int pIdx[4] = {15, 16, 17, 18};

    CvtW cw;
    for (int gg = 0; gg < 4; ++gg) {
        cw.src[gg * 3 + 0] = (const float*)d_in[wIdx[gg]];
        cw.src[gg * 3 + 1] = (const float*)d_in[uIdx[gg]];
        cw.src[gg * 3 + 2] = (const float*)d_in[pIdx[gg]];
        for (int s = 0; s < 3; ++s)
            cw.dst[gg * 3 + s] = w16 + (size_t)(gg * 3 + s) * WSZ;
    }
    CvtB cb;
    cb.src[0] = inputs; cb.dst[0] = a1h;             // x -> a1 sec0
    cb.src[1] = state;  cb.dst[1] = a1h + SECSZ;     // s -> a1 sec1
    cb.src[2] = parent; cb.dst[2] = a1h + 2 * SECSZ; // p -> a1 sec2

    CUtensorMap tmA1, tmA2, tmB;
    make_map(&tmA1, pa1, HID, BATCHSZ, 3);   // [x|s|p]
    make_map(&tmA2, pa2, HID, BATCHSZ, 2);   // [hr|pr]
    make_map(&tmB,  pw16, HID, HID, 12);

    cudaFuncSetAttribute(gru_gemm<1>, cudaFuncAttributeMaxDynamicSharedMemorySize, SMEM_BYTES);
    cudaFuncSetAttribute(gru_gemm<2>, cudaFuncAttributeMaxDynamicSharedMemorySize, SMEM_BYTES);

    GArgs a1 = {};
    a1.bias[0] = (const float*)d_in[4];
    a1.bias[1] = (const float*)d_in[6];
    a1.bias[2] = (const float*)d_in[8];
    a1.s16 = a1h + SECSZ;
    a1.p16 = a1h + 2 * SECSZ;
    a1.hr16 = a2h;
    a1.pr16 = a2h + SECSZ;
    a1.att = (__half*)patt;
    a1.state_f32 = state;
    a1.out = nullptr;

    GArgs a2 = a1;
    a2.bias[0] = (const float*)d_in[10];
    a2.bias[1] = a2.bias[0];
    a2.bias[2] = a2.bias[0];
    a2.out = (float*)d_out;

    cvt_w_kernel<<<768, 256>>>(cw);
    cvt_b_kernel<<<8192, 256>>>(cb);
    // Pass 1: gates a, r, r1  (12 N-bands of 128 over 1536 outputs)
    gru_gemm<1><<<dim3(12, BATCHSZ / BM), NTH, SMEM_BYTES>>>(tmA1, tmA2, tmB, a1);
    // Pass 2: gate c + final blend
    gru_gemm<2><<<dim3(4,  BATCHSZ / BM), NTH, SMEM_BYTES>>>(tmA1, tmA2, tmB, a2);
}